// round 1
// baseline (speedup 1.0000x reference)
#include <cuda_runtime.h>
#include <math.h>

#define NN  2048
#define TT  64
#define EE  16384
#define BB  64
#define C0  32
#define EMB 128
#define C1  64
#define C2  64
#define EPSB 1e-5f

// ---------------- scratch (device globals; no allocation allowed) ----------------
__device__ float d_h1[NN*TT*C0];     // conv1 out (16MB)
__device__ float d_a1[NN*TT*C0];     // agg1 out  (16MB)
__device__ float d_h2[NN*TT*EMB];    // gcn1 out, later gcn2 out (64MB)
__device__ float d_a2[NN*TT*EMB];    // agg2 out  (64MB)
__device__ float d_pool[NN*14*C1];   // fused conv2 out (7MB)
__device__ float d_gp[BB*14*C1];
__device__ float d_counts[BB];
__device__ int   d_rowcnt[NN];
__device__ int   d_rowstart[NN+1];
__device__ int   d_cursor[NN];
__device__ int   d_csrsrc[EE];
__device__ float d_dinv[NN];
__device__ float d_weff2[10*EMB*C1]; // pooled-collapsed conv2 weights (bn2 scale folded)
__device__ float d_beff2[C1];
__device__ float d_weff3[10*C2*C2];
__device__ float d_beff3[C2];
__device__ float d_s1[C0];
__device__ float d_b1e[C0];

// ---------------- 0: zero accumulators ----------------
__global__ void k_zero() {
    int i = blockIdx.x * blockDim.x + threadIdx.x;
    if (i < BB*14*C1) d_gp[i] = 0.f;
    if (i < NN)       d_rowcnt[i] = 0;
    if (i < BB)       d_counts[i] = 0.f;
}

// ---------------- 1: prep (degree count, batch count, folded weights) ----------------
__global__ void k_prep(const int* __restrict__ edge, const int* __restrict__ batch,
                       const float* __restrict__ g1, const float* __restrict__ b1,
                       const float* __restrict__ m1, const float* __restrict__ v1,
                       const float* __restrict__ w2, const float* __restrict__ g2,
                       const float* __restrict__ b2, const float* __restrict__ m2,
                       const float* __restrict__ v2,
                       const float* __restrict__ w3, const float* __restrict__ g3,
                       const float* __restrict__ b3, const float* __restrict__ m3,
                       const float* __restrict__ v3) {
    int i = blockIdx.x * blockDim.x + threadIdx.x;
    if (i < EE) atomicAdd(&d_rowcnt[edge[EE + i]], 1);
    if (i < NN) atomicAdd(&d_counts[batch[i]], 1.0f);
    if (i < C0) { float s = g1[i]*rsqrtf(v1[i]+EPSB); d_s1[i]=s; d_b1e[i]=b1[i]-m1[i]*s; }
    if (i < C1) { float s = g2[i]*rsqrtf(v2[i]+EPSB); d_beff2[i]=b2[i]-m2[i]*s; }
    if (i < C2) { float s = g3[i]*rsqrtf(v3[i]+EPSB); d_beff3[i]=b3[i]-m3[i]*s; }
    if (i < 10*EMB*C1) {
        int c = i % C1; int ci = (i / C1) % EMB; int u = i / (C1*EMB);
        float s = g2[c]*rsqrtf(v2[c]+EPSB);
        int klo = u-3; if (klo < 0) klo = 0;
        int khi = u < 6 ? u : 6;
        float acc = 0.f;
        for (int k = klo; k <= khi; k++) acc += w2[(k*EMB+ci)*C1 + c];
        d_weff2[i] = acc * s * 0.25f;
    }
    if (i < 10*C2*C2) {
        int c = i % C2; int ci = (i / C2) % C2; int u = i / (C2*C2);
        float s = g3[c]*rsqrtf(v3[c]+EPSB);
        int klo = u-3; if (klo < 0) klo = 0;
        int khi = u < 6 ? u : 6;
        float acc = 0.f;
        for (int k = klo; k <= khi; k++) acc += w3[(k*C2+ci)*C2 + c];
        d_weff3[i] = acc * s * 0.25f;
    }
}

// ---------------- 2: prefix scan -> CSR row starts, dinv ----------------
__global__ void k_scan() {
    __shared__ int sa[NN], sb[NN];
    int t = threadIdx.x;                       // 1024 threads
    sa[t] = d_rowcnt[t]; sa[t+1024] = d_rowcnt[t+1024];
    __syncthreads();
    int* cur = sa; int* nxt = sb;
    for (int off = 1; off < NN; off <<= 1) {
        for (int j = t; j < NN; j += 1024) {
            int v = cur[j];
            if (j >= off) v += cur[j-off];
            nxt[j] = v;
        }
        __syncthreads();
        int* tmp = cur; cur = nxt; nxt = tmp;
    }
    for (int j = t; j < NN; j += 1024) {
        int excl = (j == 0) ? 0 : cur[j-1];
        d_rowstart[j] = excl;
        d_cursor[j]   = excl;
        d_dinv[j]     = rsqrtf((float)(d_rowcnt[j] + 1));
        if (j == NN-1) d_rowstart[NN] = cur[NN-1];
    }
}

// ---------------- 3: scatter edges into CSR ----------------
__global__ void k_scatter(const int* __restrict__ edge) {
    int e = blockIdx.x * blockDim.x + threadIdx.x;
    if (e < EE) {
        int dd = edge[EE + e];
        int pos = atomicAdd(&d_cursor[dd], 1);
        d_csrsrc[pos] = edge[e];
    }
}

// ---------------- 4: conv1 + bn1 + relu: (N,T) -> (N,T,32) ----------------
__global__ void k_conv1(const float* __restrict__ x, const float* __restrict__ w) {
    __shared__ float xs[TT];
    __shared__ float ws[7*C0];
    __shared__ float ss[C0], bs[C0];
    int n = blockIdx.x, tid = threadIdx.x;     // 256 threads
    if (tid < TT)   xs[tid] = x[n*TT + tid];
    if (tid < 7*C0) ws[tid] = w[tid];
    if (tid < C0) { ss[tid] = d_s1[tid]; bs[tid] = d_b1e[tid]; }
    __syncthreads();
    int c = tid & 31, t0 = tid >> 5;
    for (int t = t0; t < TT; t += 8) {
        float acc = 0.f;
        #pragma unroll
        for (int k = 0; k < 7; k++) {
            int ti = t + k - 3;
            if (ti >= 0 && ti < TT) acc += xs[ti] * ws[k*C0 + c];
        }
        acc = acc * ss[c] + bs[c];
        d_h1[(n*TT + t)*C0 + c] = fmaxf(acc, 0.f);
    }
}

// ---------------- 5/7: CSR aggregation  out[i] = sum_j norm_ij * in[j] ----------------
__global__ void k_agg1() {           // rows of 2048 floats (h1 -> a1)
    int node = blockIdx.x;
    int off  = threadIdx.x * 4;      // 256 threads * 4, plus +1024
    float di = d_dinv[node];
    float w  = di * di;
    const float* base = d_h1 + (size_t)node*2048 + off;
    float4 v0 = *(const float4*)base;
    float4 v1 = *(const float4*)(base + 1024);
    float4 a0 = make_float4(v0.x*w, v0.y*w, v0.z*w, v0.w*w);
    float4 a1 = make_float4(v1.x*w, v1.y*w, v1.z*w, v1.w*w);
    int e0 = d_rowstart[node], e1 = d_rowstart[node+1];
    for (int e = e0; e < e1; e++) {
        int s = d_csrsrc[e];
        float ww = di * d_dinv[s];
        const float* sb = d_h1 + (size_t)s*2048 + off;
        float4 u0 = *(const float4*)sb;
        float4 u1 = *(const float4*)(sb + 1024);
        a0.x += ww*u0.x; a0.y += ww*u0.y; a0.z += ww*u0.z; a0.w += ww*u0.w;
        a1.x += ww*u1.x; a1.y += ww*u1.y; a1.z += ww*u1.z; a1.w += ww*u1.w;
    }
    float* ob = d_a1 + (size_t)node*2048 + off;
    *(float4*)ob = a0;
    *(float4*)(ob + 1024) = a1;
}

__global__ void k_agg2() {           // rows of 8192 floats (h2 -> a2), grid.y = 4 chunks
    int node = blockIdx.x;
    int off  = blockIdx.y*2048 + threadIdx.x*4;
    float di = d_dinv[node];
    float w  = di * di;
    const float* base = d_h2 + (size_t)node*8192 + off;
    float4 v0 = *(const float4*)base;
    float4 v1 = *(const float4*)(base + 1024);
    float4 a0 = make_float4(v0.x*w, v0.y*w, v0.z*w, v0.w*w);
    float4 a1 = make_float4(v1.x*w, v1.y*w, v1.z*w, v1.w*w);
    int e0 = d_rowstart[node], e1 = d_rowstart[node+1];
    for (int e = e0; e < e1; e++) {
        int s = d_csrsrc[e];
        float ww = di * d_dinv[s];
        const float* sb = d_h2 + (size_t)s*8192 + off;
        float4 u0 = *(const float4*)sb;
        float4 u1 = *(const float4*)(sb + 1024);
        a0.x += ww*u0.x; a0.y += ww*u0.y; a0.z += ww*u0.z; a0.w += ww*u0.w;
        a1.x += ww*u1.x; a1.y += ww*u1.y; a1.z += ww*u1.z; a1.w += ww*u1.w;
    }
    float* ob = d_a2 + (size_t)node*8192 + off;
    *(float4*)ob = a0;
    *(float4*)(ob + 1024) = a1;
}

// ---------------- 6: gcn1 matmul (131072,32)@(32,128) + bias + relu ----------------
__global__ void k_mm1(const float* __restrict__ W, const float* __restrict__ bias) {
    __shared__ float Ws[C0*EMB];   // 16KB
    __shared__ float As[64*C0];    // 8KB
    int tid = threadIdx.x;         // 256
    for (int i = tid; i < C0*EMB; i += 256) Ws[i] = W[i];
    int rowbase = blockIdx.x * 64;
    for (int i = tid; i < 64*C0; i += 256) As[i] = d_a1[(size_t)rowbase*C0 + i];
    __syncthreads();
    int c = tid & 127, rh = tid >> 7;
    float wreg[C0];
    #pragma unroll
    for (int k = 0; k < C0; k++) wreg[k] = Ws[k*EMB + c];
    float b = bias[c];
    for (int rr = 0; rr < 32; rr++) {
        const float* ap = &As[(rh*32 + rr)*C0];
        float acc = b;
        #pragma unroll
        for (int k = 0; k < C0; k += 4) {
            float4 a = *(const float4*)(ap + k);
            acc += a.x*wreg[k] + a.y*wreg[k+1] + a.z*wreg[k+2] + a.w*wreg[k+3];
        }
        d_h2[(size_t)(rowbase + rh*32 + rr)*EMB + c] = fmaxf(acc, 0.f);
    }
}

// ---------------- 8: gcn2 matmul (131072,128)@(128,128) + bias + relu ----------------
__global__ void k_mm2(const float* __restrict__ W, const float* __restrict__ bias) {
    __shared__ float As[64*32];    // 8KB
    __shared__ float Bs[32*EMB];   // 16KB
    int tid = threadIdx.x;         // 256
    int rowbase = blockIdx.x * 64;
    int tx = tid & 31, ty = tid >> 5;
    float acc[8][4];
    float4 bv = *(const float4*)&bias[tx*4];
    #pragma unroll
    for (int i = 0; i < 8; i++) { acc[i][0]=bv.x; acc[i][1]=bv.y; acc[i][2]=bv.z; acc[i][3]=bv.w; }
    for (int kc = 0; kc < 4; kc++) {
        for (int i = tid; i < 2048; i += 256) {
            int r = i >> 5, k = i & 31;
            As[i] = d_a2[(size_t)(rowbase + r)*EMB + kc*32 + k];
        }
        for (int i = tid; i < 4096; i += 256) {
            int k = i >> 7, c = i & 127;
            Bs[i] = W[(kc*32 + k)*EMB + c];
        }
        __syncthreads();
        for (int k = 0; k < 32; k++) {
            float ar[8];
            #pragma unroll
            for (int i = 0; i < 8; i++) ar[i] = As[(ty*8 + i)*32 + k];
            float4 br = *(const float4*)&Bs[k*EMB + tx*4];
            #pragma unroll
            for (int i = 0; i < 8; i++) {
                acc[i][0] += ar[i]*br.x; acc[i][1] += ar[i]*br.y;
                acc[i][2] += ar[i]*br.z; acc[i][3] += ar[i]*br.w;
            }
        }
        __syncthreads();
    }
    #pragma unroll
    for (int i = 0; i < 8; i++) {
        size_t rb = (size_t)(rowbase + ty*8 + i)*EMB + tx*4;
        d_h2[rb+0] = fmaxf(acc[i][0], 0.f);
        d_h2[rb+1] = fmaxf(acc[i][1], 0.f);
        d_h2[rb+2] = fmaxf(acc[i][2], 0.f);
        d_h2[rb+3] = fmaxf(acc[i][3], 0.f);
    }
}

// ---------------- 9: fused conv2+bn2+avgpool+relu: (N,64,128) -> (N,14,64) ----------------
__global__ void k_conv2() {
    __shared__ float hs[62*EMB];   // 31KB: rows t=0..61
    __shared__ float Wsm[64*C1];   // 16KB
    int n = blockIdx.x, tid = threadIdx.x;      // 224 threads = 14p x 16g
    for (int i = tid; i < 62*EMB; i += 224) hs[i] = d_h2[(size_t)n*TT*EMB + i];
    int p = tid >> 4, g = tid & 15;
    float acc[4];
    #pragma unroll
    for (int j = 0; j < 4; j++) acc[j] = d_beff2[g*4 + j];
    for (int u = 0; u < 10; u++) {
        for (int h = 0; h < 2; h++) {
            __syncthreads();
            for (int i = tid; i < 64*C1; i += 224)
                Wsm[i] = d_weff2[(u*EMB + h*64)*C1 + i];
            __syncthreads();
            int hbase = (4*p + u)*EMB + h*64;
            #pragma unroll 8
            for (int ci = 0; ci < 64; ci++) {
                float hv = hs[hbase + ci];
                float4 w = *(const float4*)&Wsm[ci*C1 + g*4];
                acc[0] += hv*w.x; acc[1] += hv*w.y; acc[2] += hv*w.z; acc[3] += hv*w.w;
            }
        }
    }
    size_t ob = (size_t)n*14*C1 + p*C1 + g*4;
    #pragma unroll
    for (int j = 0; j < 4; j++) d_pool[ob + j] = fmaxf(acc[j], 0.f);
}

// ---------------- 10: graph sum pool (atomic) ----------------
__global__ void k_gpool(const int* __restrict__ batch) {
    int i = blockIdx.x * blockDim.x + threadIdx.x;
    if (i < NN*14*C1) {
        int n = i / (14*C1);
        int rem = i - n*14*C1;
        atomicAdd(&d_gp[batch[n]*14*C1 + rem], d_pool[i]);
    }
}

// ---------------- 11: conv3+bn3+pool+relu + dense + log_softmax ----------------
__global__ void k_final(const float* __restrict__ dw, const float* __restrict__ db,
                        float* __restrict__ out) {
    __shared__ float gin[14*C1];
    __shared__ float flat[128];
    __shared__ float lg[4];
    int b = blockIdx.x, tid = threadIdx.x;     // 128 threads
    float inv = 1.f / d_counts[b];
    for (int i = tid; i < 14*C1; i += 128) gin[i] = d_gp[b*14*C1 + i] * inv;
    __syncthreads();
    int p = tid >> 6, c = tid & 63;
    float acc = d_beff3[c];
    for (int u = 0; u < 10; u++)
        for (int ci = 0; ci < C2; ci++)
            acc += gin[(4*p + u)*C2 + ci] * d_weff3[(u*C2 + ci)*C2 + c];
    flat[p*64 + c] = fmaxf(acc, 0.f);
    __syncthreads();
    if (tid < 4) {
        float a = db[tid];
        for (int i = 0; i < 128; i++) a += flat[i] * dw[i*4 + tid];
        lg[tid] = a;
    }
    __syncthreads();
    if (tid == 0) {
        float m = fmaxf(fmaxf(lg[0], lg[1]), fmaxf(lg[2], lg[3]));
        float se = expf(lg[0]-m) + expf(lg[1]-m) + expf(lg[2]-m) + expf(lg[3]-m);
        float lse = logf(se) + m;
        for (int j = 0; j < 4; j++) out[b*4 + j] = lg[j] - lse;
    }
}

// ---------------- launcher ----------------
extern "C" void kernel_launch(void* const* d_in, const int* in_sizes, int n_in,
                              void* d_out, int out_size) {
    const float* x       = (const float*)d_in[0];
    const int*   edge    = (const int*)d_in[1];
    const int*   batch   = (const int*)d_in[2];
    const float* conv1_w = (const float*)d_in[3];
    const float* bn1_g   = (const float*)d_in[4];
    const float* bn1_b   = (const float*)d_in[5];
    const float* bn1_m   = (const float*)d_in[6];
    const float* bn1_v   = (const float*)d_in[7];
    const float* gcn1_w  = (const float*)d_in[8];
    const float* gcn1_b  = (const float*)d_in[9];
    const float* gcn2_w  = (const float*)d_in[10];
    const float* gcn2_b  = (const float*)d_in[11];
    const float* conv2_w = (const float*)d_in[12];
    const float* bn2_g   = (const float*)d_in[13];
    const float* bn2_b   = (const float*)d_in[14];
    const float* bn2_m   = (const float*)d_in[15];
    const float* bn2_v   = (const float*)d_in[16];
    const float* conv3_w = (const float*)d_in[17];
    const float* bn3_g   = (const float*)d_in[18];
    const float* bn3_b   = (const float*)d_in[19];
    const float* bn3_m   = (const float*)d_in[20];
    const float* bn3_v   = (const float*)d_in[21];
    const float* dense_w = (const float*)d_in[22];
    const float* dense_b = (const float*)d_in[23];
    float* out = (float*)d_out;

    k_zero<<<224, 256>>>();
    k_prep<<<320, 256>>>(edge, batch, bn1_g, bn1_b, bn1_m, bn1_v,
                         conv2_w, bn2_g, bn2_b, bn2_m, bn2_v,
                         conv3_w, bn3_g, bn3_b, bn3_m, bn3_v);
    k_scan<<<1, 1024>>>();
    k_scatter<<<64, 256>>>(edge);
    k_conv1<<<NN, 256>>>(x, conv1_w);
    k_agg1<<<NN, 256>>>();
    k_mm1<<<NN, 256>>>(gcn1_w, gcn1_b);
    k_agg2<<<dim3(NN, 4), 256>>>();
    k_mm2<<<NN, 256>>>(gcn2_w, gcn2_b);
    k_conv2<<<NN, 224>>>();
    k_gpool<<<7168, 256>>>(batch);
    k_final<<<BB, 128>>>(dense_w, dense_b, out);
}